// round 1
// baseline (speedup 1.0000x reference)
#include <cuda_runtime.h>
#include <math.h>

// Problem constants
// B=8, n=1024, dQ=dV=512, H=8, d=64, HB=64
#define NSEQ   1024
#define DHEAD  64
#define DVTOT  512
#define NBATCH 8
#define NHB    64

// 1/sqrt(512)
#define SSCALE 0.044194173824159216f
// log(1/1024 + 1e-8)
#define LOGMU  (-6.9314615657f)

// Scratch (device globals; no allocation allowed)
__device__ float g_Qh[NHB * NSEQ * DHEAD];   // head-major Q_  [64][1024][64]
__device__ float g_Oh[NHB * NSEQ * DHEAD];   // head-major O_  [64][1024][64]
__device__ float g_u[NHB * NSEQ];
__device__ float g_v[NHB * NSEQ];
__device__ float g_X[NBATCH * NSEQ * DVTOT]; // after merge + LN0
__device__ float g_T[NBATCH * NSEQ * DVTOT]; // X + relu(X Wo^T + bo)

// ---------------------------------------------------------------------------
// helpers
// ---------------------------------------------------------------------------
__device__ __forceinline__ unsigned tf32b(float x) {
    unsigned r;
    asm("cvt.rna.tf32.f32 %0, %1;" : "=r"(r) : "f"(x));
    return r;
}
__device__ __forceinline__ float tf32f(float x) {
    return __uint_as_float(tf32b(x));
}
__device__ __forceinline__ void mma8(float* c, const unsigned* a, const unsigned* b) {
    asm volatile(
        "mma.sync.aligned.m16n8k8.row.col.f32.tf32.tf32.f32 "
        "{%0,%1,%2,%3},{%4,%5,%6,%7},{%8,%9},{%0,%1,%2,%3};\n"
        : "+f"(c[0]), "+f"(c[1]), "+f"(c[2]), "+f"(c[3])
        : "r"(a[0]), "r"(a[1]), "r"(a[2]), "r"(a[3]), "r"(b[0]), "r"(b[1]));
}

// ---------------------------------------------------------------------------
// GEMM: C[8192,512] = A[8192,512] * W[512,512]^T (+bias, epilogues)
// MODE 0: A = Q input; scatter-store head-major into g_Qh (Qp projection)
// MODE 1: A = g_X;  g_T = g_X + relu(C + bias)                (FFN)
// 256 threads, tile 128x128, BK=16, warps 4(m) x 2(n), each warp 32x64
// ---------------------------------------------------------------------------
template <int MODE>
__global__ void __launch_bounds__(256) gemm512_kernel(const float* __restrict__ Ain,
                                                      const float* __restrict__ W,
                                                      const float* __restrict__ bias) {
    __shared__ float As[128 * 20];
    __shared__ float Bs[128 * 20];
    const float* A = (MODE == 0) ? Ain : (const float*)g_X;

    const int m0 = blockIdx.y * 128, n0 = blockIdx.x * 128;
    const int tid = threadIdx.x, lane = tid & 31, w = tid >> 5;
    const int wm = (w & 3) * 32, wn = (w >> 2) * 64;

    float acc[2][8][4];
#pragma unroll
    for (int a = 0; a < 2; a++)
#pragma unroll
        for (int b = 0; b < 8; b++)
#pragma unroll
            for (int c = 0; c < 4; c++) acc[a][b][c] = 0.f;

    for (int k0 = 0; k0 < 512; k0 += 16) {
        __syncthreads();
#pragma unroll
        for (int r = 0; r < 2; r++) {
            int idx = tid * 2 + r;             // 0..511
            int row = idx >> 2, kq = (idx & 3) * 4;
            float4 va = *(const float4*)(A + (size_t)(m0 + row) * 512 + k0 + kq);
            As[row * 20 + kq + 0] = tf32f(va.x);
            As[row * 20 + kq + 1] = tf32f(va.y);
            As[row * 20 + kq + 2] = tf32f(va.z);
            As[row * 20 + kq + 3] = tf32f(va.w);
            float4 vb = *(const float4*)(W + (size_t)(n0 + row) * 512 + k0 + kq);
            Bs[row * 20 + kq + 0] = tf32f(vb.x);
            Bs[row * 20 + kq + 1] = tf32f(vb.y);
            Bs[row * 20 + kq + 2] = tf32f(vb.z);
            Bs[row * 20 + kq + 3] = tf32f(vb.w);
        }
        __syncthreads();
#pragma unroll
        for (int kk = 0; kk < 2; kk++) {
            int kb = kk * 8;
            int kc = kb + (lane & 3);
            unsigned af[2][4];
#pragma unroll
            for (int mt = 0; mt < 2; mt++) {
                int r = wm + mt * 16 + (lane >> 2);
                af[mt][0] = __float_as_uint(As[r * 20 + kc]);
                af[mt][1] = __float_as_uint(As[(r + 8) * 20 + kc]);
                af[mt][2] = __float_as_uint(As[r * 20 + kc + 4]);
                af[mt][3] = __float_as_uint(As[(r + 8) * 20 + kc + 4]);
            }
#pragma unroll
            for (int nt = 0; nt < 8; nt++) {
                int c = wn + nt * 8 + (lane >> 2);
                unsigned bf[2];
                bf[0] = __float_as_uint(Bs[c * 20 + kc]);
                bf[1] = __float_as_uint(Bs[c * 20 + kc + 4]);
#pragma unroll
                for (int mt = 0; mt < 2; mt++) mma8(acc[mt][nt], af[mt], bf);
            }
        }
    }

#pragma unroll
    for (int mt = 0; mt < 2; mt++)
#pragma unroll
        for (int nt = 0; nt < 8; nt++)
#pragma unroll
            for (int rg = 0; rg < 4; rg++) {
                int row = m0 + wm + mt * 16 + (lane >> 2) + ((rg & 2) ? 8 : 0);
                int col = n0 + wn + nt * 8 + 2 * (lane & 3) + (rg & 1);
                float v = acc[mt][nt][rg] + bias[col];
                if (MODE == 0) {
                    int b = row >> 10, i = row & 1023;
                    int h = col >> 6, dc = col & 63;
                    g_Qh[(((h << 3) + b) * NSEQ + i) * DHEAD + dc] = v;
                } else {
                    v = fmaxf(v, 0.f) + A[(size_t)row * 512 + col];
                    g_T[(size_t)row * 512 + col] = v;
                }
            }
}

// ---------------------------------------------------------------------------
// Sinkhorn LSE passes (flash-style recompute of S = Q_ Q_^T / sqrt(512)).
// ADDU=false: u_i = log_mu - log(sum_j exp(S_ij))                 -> g_u
// ADDU=true : v_j = log_mu - log(sum_i exp(S_ji + u_i))  (S sym.) -> g_v
// grid (8 row-blocks, 64 bh), 256 threads, warps 4(m) x 2(j)
// ---------------------------------------------------------------------------
template <bool ADDU>
__global__ void __launch_bounds__(256) sink_lse_kernel() {
    extern __shared__ float sm[];
    float* Qi = sm;                 // 128*72
    float* Qj = sm + 9216;          // 128*72
    float* ub = sm + 18432;         // 128
    float* ps = sm + 18560;         // 256

    const int bh = blockIdx.y;
    const int i0 = blockIdx.x * 128;
    const int tid = threadIdx.x, lane = tid & 31, w = tid >> 5;
    const int wm = (w & 3) * 32, wn = (w >> 2) * 64;
    const float* Qbase = g_Qh + (size_t)bh * (NSEQ * DHEAD);

#pragma unroll
    for (int r = 0; r < 8; r++) {
        int idx = tid + r * 256;
        int row = idx >> 4, q = (idx & 15) * 4;
        float4 v = *(const float4*)(Qbase + (i0 + row) * DHEAD + q);
        float4 t;
        t.x = tf32f(v.x); t.y = tf32f(v.y); t.z = tf32f(v.z); t.w = tf32f(v.w);
        *(float4*)(Qi + row * 72 + q) = t;
    }

    float ls[2][2] = {{0.f, 0.f}, {0.f, 0.f}};

    for (int jt = 0; jt < 8; jt++) {
        int j0 = jt * 128;
        __syncthreads();
#pragma unroll
        for (int r = 0; r < 8; r++) {
            int idx = tid + r * 256;
            int row = idx >> 4, q = (idx & 15) * 4;
            float4 v = *(const float4*)(Qbase + (j0 + row) * DHEAD + q);
            float4 t;
            t.x = tf32f(v.x); t.y = tf32f(v.y); t.z = tf32f(v.z); t.w = tf32f(v.w);
            *(float4*)(Qj + row * 72 + q) = t;
        }
        if (ADDU && tid < 128) ub[tid] = g_u[bh * NSEQ + j0 + tid];
        __syncthreads();

        float sa[2][8][4];
#pragma unroll
        for (int a = 0; a < 2; a++)
#pragma unroll
            for (int b = 0; b < 8; b++)
#pragma unroll
                for (int c = 0; c < 4; c++) sa[a][b][c] = 0.f;

#pragma unroll
        for (int kk = 0; kk < 8; kk++) {
            int kb = kk * 8;
            int kc = kb + (lane & 3);
            unsigned af[2][4];
#pragma unroll
            for (int mt = 0; mt < 2; mt++) {
                int r = wm + mt * 16 + (lane >> 2);
                af[mt][0] = __float_as_uint(Qi[r * 72 + kc]);
                af[mt][1] = __float_as_uint(Qi[(r + 8) * 72 + kc]);
                af[mt][2] = __float_as_uint(Qi[r * 72 + kc + 4]);
                af[mt][3] = __float_as_uint(Qi[(r + 8) * 72 + kc + 4]);
            }
#pragma unroll
            for (int nt = 0; nt < 8; nt++) {
                int c = wn + nt * 8 + (lane >> 2);
                unsigned bf[2];
                bf[0] = __float_as_uint(Qj[c * 72 + kc]);
                bf[1] = __float_as_uint(Qj[c * 72 + kc + 4]);
#pragma unroll
                for (int mt = 0; mt < 2; mt++) mma8(sa[mt][nt], af[mt], bf);
            }
        }
        // accumulate exp sums (no running max needed: |S| <= ~6)
#pragma unroll
        for (int mt = 0; mt < 2; mt++)
#pragma unroll
            for (int nt = 0; nt < 8; nt++)
#pragma unroll
                for (int rg = 0; rg < 4; rg++) {
                    float v = sa[mt][nt][rg] * SSCALE;
                    if (ADDU) v += ub[wn + nt * 8 + 2 * (lane & 3) + (rg & 1)];
                    ls[mt][rg >> 1] += __expf(v);
                }
    }

    // reduce over the 4 lanes that share a row, then across the 2 column-warps
#pragma unroll
    for (int mt = 0; mt < 2; mt++)
#pragma unroll
        for (int h = 0; h < 2; h++) {
            float v = ls[mt][h];
            v += __shfl_xor_sync(0xffffffffu, v, 1);
            v += __shfl_xor_sync(0xffffffffu, v, 2);
            if ((lane & 3) == 0)
                ps[(w >> 2) * 128 + wm + mt * 16 + (lane >> 2) + h * 8] = v;
        }
    __syncthreads();
    if (tid < 128) {
        float s = ps[tid] + ps[128 + tid];
        float r = LOGMU - __logf(s);
        if (ADDU) g_v[bh * NSEQ + i0 + tid] = r;
        else      g_u[bh * NSEQ + i0 + tid] = r;
    }
}

// ---------------------------------------------------------------------------
// Pass C: O_ = Q_ + (1024 * exp(S + u_i + v_j)) @ Q_
// Phase 1 per j-tile: S via mma (warps 4m x 2j), exp -> A tile in smem (tf32)
// Phase 2: O += A @ Qj via mma (warps 4m x 2d), O accum persistent
// ---------------------------------------------------------------------------
__global__ void __launch_bounds__(256) sink_av_kernel() {
    extern __shared__ float sm[];
    float* Qi = sm;                  // 128*72
    float* Qj = sm + 9216;           // 128*72
    float* Ap = sm + 18432;          // 128*132
    float* ur = sm + 35328;          // 128
    float* vb = sm + 35456;          // 128

    const int bh = blockIdx.y;
    const int i0 = blockIdx.x * 128;
    const int tid = threadIdx.x, lane = tid & 31, w = tid >> 5;
    const int wm = (w & 3) * 32;
    const int wn = (w >> 2) * 64;    // phase 1 (j cols)
    const int wn2 = (w >> 2) * 32;   // phase 2 (d cols)
    const float* Qbase = g_Qh + (size_t)bh * (NSEQ * DHEAD);
    float* Obase = g_Oh + (size_t)bh * (NSEQ * DHEAD);

#pragma unroll
    for (int r = 0; r < 8; r++) {
        int idx = tid + r * 256;
        int row = idx >> 4, q = (idx & 15) * 4;
        float4 v = *(const float4*)(Qbase + (i0 + row) * DHEAD + q);
        float4 t;
        t.x = tf32f(v.x); t.y = tf32f(v.y); t.z = tf32f(v.z); t.w = tf32f(v.w);
        *(float4*)(Qi + row * 72 + q) = t;
    }
    if (tid < 128) ur[tid] = g_u[bh * NSEQ + i0 + tid];

    float oa[2][4][4];
#pragma unroll
    for (int a = 0; a < 2; a++)
#pragma unroll
        for (int b = 0; b < 4; b++)
#pragma unroll
            for (int c = 0; c < 4; c++) oa[a][b][c] = 0.f;

    for (int jt = 0; jt < 8; jt++) {
        int j0 = jt * 128;
        __syncthreads();
#pragma unroll
        for (int r = 0; r < 8; r++) {
            int idx = tid + r * 256;
            int row = idx >> 4, q = (idx & 15) * 4;
            float4 v = *(const float4*)(Qbase + (j0 + row) * DHEAD + q);
            float4 t;
            t.x = tf32f(v.x); t.y = tf32f(v.y); t.z = tf32f(v.z); t.w = tf32f(v.w);
            *(float4*)(Qj + row * 72 + q) = t;
        }
        if (tid < 128) vb[tid] = g_v[bh * NSEQ + j0 + tid];
        __syncthreads();

        // ---- phase 1: S tile ----
        float sa[2][8][4];
#pragma unroll
        for (int a = 0; a < 2; a++)
#pragma unroll
            for (int b = 0; b < 8; b++)
#pragma unroll
                for (int c = 0; c < 4; c++) sa[a][b][c] = 0.f;

#pragma unroll
        for (int kk = 0; kk < 8; kk++) {
            int kb = kk * 8;
            int kc = kb + (lane & 3);
            unsigned af[2][4];
#pragma unroll
            for (int mt = 0; mt < 2; mt++) {
                int r = wm + mt * 16 + (lane >> 2);
                af[mt][0] = __float_as_uint(Qi[r * 72 + kc]);
                af[mt][1] = __float_as_uint(Qi[(r + 8) * 72 + kc]);
                af[mt][2] = __float_as_uint(Qi[r * 72 + kc + 4]);
                af[mt][3] = __float_as_uint(Qi[(r + 8) * 72 + kc + 4]);
            }
#pragma unroll
            for (int nt = 0; nt < 8; nt++) {
                int c = wn + nt * 8 + (lane >> 2);
                unsigned bf[2];
                bf[0] = __float_as_uint(Qj[c * 72 + kc]);
                bf[1] = __float_as_uint(Qj[c * 72 + kc + 4]);
#pragma unroll
                for (int mt = 0; mt < 2; mt++) mma8(sa[mt][nt], af[mt], bf);
            }
        }
        // A = 1024 * exp(S*scale + u_i + v_j), stored as tf32 in smem
#pragma unroll
        for (int mt = 0; mt < 2; mt++)
#pragma unroll
            for (int nt = 0; nt < 8; nt++)
#pragma unroll
                for (int rg = 0; rg < 4; rg++) {
                    int row = wm + mt * 16 + (lane >> 2) + ((rg & 2) ? 8 : 0);
                    int col = wn + nt * 8 + 2 * (lane & 3) + (rg & 1);
                    float p = 1024.f * __expf(sa[mt][nt][rg] * SSCALE + ur[row] + vb[col]);
                    Ap[row * 132 + col] = tf32f(p);
                }
        __syncthreads();

        // ---- phase 2: O += A @ Qj ----
#pragma unroll
        for (int kk = 0; kk < 16; kk++) {
            int kb = kk * 8;
            int kc = kb + (lane & 3);
            unsigned af[2][4];
#pragma unroll
            for (int mt = 0; mt < 2; mt++) {
                int r = wm + mt * 16 + (lane >> 2);
                af[mt][0] = __float_as_uint(Ap[r * 132 + kc]);
                af[mt][1] = __float_as_uint(Ap[(r + 8) * 132 + kc]);
                af[mt][2] = __float_as_uint(Ap[r * 132 + kc + 4]);
                af[mt][3] = __float_as_uint(Ap[(r + 8) * 132 + kc + 4]);
            }
#pragma unroll
            for (int nt = 0; nt < 4; nt++) {
                int c = wn2 + nt * 8 + (lane >> 2);
                unsigned bf[2];
                bf[0] = __float_as_uint(Qj[kc * 72 + c]);
                bf[1] = __float_as_uint(Qj[(kc + 4) * 72 + c]);
#pragma unroll
                for (int mt = 0; mt < 2; mt++) mma8(oa[mt][nt], af[mt], bf);
            }
        }
    }

    // epilogue: O_ = Q_ + accum  (Q_ read at full fp32)
#pragma unroll
    for (int mt = 0; mt < 2; mt++)
#pragma unroll
        for (int nt = 0; nt < 4; nt++)
#pragma unroll
            for (int rg = 0; rg < 4; rg++) {
                int row = i0 + wm + mt * 16 + (lane >> 2) + ((rg & 2) ? 8 : 0);
                int col = wn2 + nt * 8 + 2 * (lane & 3) + (rg & 1);
                Obase[row * DHEAD + col] = oa[mt][nt][rg] + Qbase[row * DHEAD + col];
            }
}

// ---------------------------------------------------------------------------
// LayerNorm kernels. mode 0: merge heads from g_Oh -> LN -> g_X
//                    mode 1: g_T -> LN -> out
// one block per (b,i) row, 512 threads
// ---------------------------------------------------------------------------
__global__ void __launch_bounds__(512) ln_kernel(const float* __restrict__ gg,
                                                 const float* __restrict__ bb,
                                                 float* __restrict__ out, int mode) {
    int m = blockIdx.x;
    int t = threadIdx.x;
    float val;
    if (mode == 0) {
        int b = m >> 10, i = m & 1023, h = t >> 6, dc = t & 63;
        val = g_Oh[(((h << 3) + b) * NSEQ + i) * DHEAD + dc];
    } else {
        val = g_T[(size_t)m * 512 + t];
    }
    float s = val, q = val * val;
#pragma unroll
    for (int off = 16; off; off >>= 1) {
        s += __shfl_xor_sync(0xffffffffu, s, off);
        q += __shfl_xor_sync(0xffffffffu, q, off);
    }
    __shared__ float ss[16], sq[16];
    int w = t >> 5, lane = t & 31;
    if (!lane) { ss[w] = s; sq[w] = q; }
    __syncthreads();
    float S = 0.f, Q2 = 0.f;
#pragma unroll
    for (int k = 0; k < 16; k++) { S += ss[k]; Q2 += sq[k]; }
    float mean = S * (1.f / 512.f);
    float var = Q2 * (1.f / 512.f) - mean * mean;
    float y = (val - mean) * rsqrtf(var + 1e-5f) * gg[t] + bb[t];
    if (mode == 0) g_X[(size_t)m * 512 + t] = y;
    else           out[(size_t)m * 512 + t] = y;
}

// ---------------------------------------------------------------------------
extern "C" void kernel_launch(void* const* d_in, const int* in_sizes, int n_in,
                              void* d_out, int out_size) {
    (void)in_sizes; (void)n_in; (void)out_size;
    const float* Q  = (const float*)d_in[0];
    // d_in[1] = K, unused by the reference forward
    const float* Wq = (const float*)d_in[2];
    const float* bq = (const float*)d_in[3];
    const float* Wo = (const float*)d_in[4];
    const float* bo = (const float*)d_in[5];
    const float* g0 = (const float*)d_in[6];
    const float* b0 = (const float*)d_in[7];
    const float* g1 = (const float*)d_in[8];
    const float* b1 = (const float*)d_in[9];
    float* out = (float*)d_out;

    const int SMEM_LSE = (9216 * 2 + 128 + 256) * 4;        // 75264 B
    const int SMEM_AV  = (9216 * 2 + 16896 + 256) * 4;      // 142336 B
    cudaFuncSetAttribute(sink_lse_kernel<false>,
                         cudaFuncAttributeMaxDynamicSharedMemorySize, SMEM_LSE);
    cudaFuncSetAttribute(sink_lse_kernel<true>,
                         cudaFuncAttributeMaxDynamicSharedMemorySize, SMEM_LSE);
    cudaFuncSetAttribute(sink_av_kernel,
                         cudaFuncAttributeMaxDynamicSharedMemorySize, SMEM_AV);

    dim3 ggrid(4, 64);   // N/128, M/128
    dim3 agrid(8, 64);   // row-blocks, bh

    gemm512_kernel<0><<<ggrid, 256>>>(Q, Wq, bq);
    sink_lse_kernel<false><<<agrid, 256, SMEM_LSE>>>();
    sink_lse_kernel<true><<<agrid, 256, SMEM_LSE>>>();
    sink_av_kernel<<<agrid, 256, SMEM_AV>>>();
    ln_kernel<<<8192, 512>>>(g0, b0, nullptr, 0);
    gemm512_kernel<1><<<ggrid, 256>>>(nullptr, Wo, bo);
    ln_kernel<<<8192, 512>>>(g1, b1, out, 1);
}

// round 2
// speedup vs baseline: 1.7199x; 1.7199x over previous
#include <cuda_runtime.h>
#include <cuda_fp16.h>
#include <math.h>

// Problem constants: B=8, n=1024, dQ=dV=512, H=8, d=64, HB=64
#define NSEQ   1024
#define DHEAD  64
#define DVTOT  512
#define NBATCH 8
#define NHB    64

#define SSCALE 0.044194173824159216f   // 1/sqrt(512)
#define LOGMU  (-6.9314615657f)        // log(1/1024 + 1e-8)

// Scratch (device globals; no allocation allowed)
__device__ float  g_Qh [NHB * NSEQ * DHEAD];   // head-major Q_ fp32 (residual)
__device__ __half g_Qh16[NHB * NSEQ * DHEAD];  // head-major Q_ fp16 (mma operand)
__device__ float  g_Oh [NHB * NSEQ * DHEAD];   // head-major O_
__device__ float  g_u  [NHB * NSEQ];
__device__ float  g_v  [NHB * NSEQ];
__device__ float  g_X  [NBATCH * NSEQ * DVTOT];
__device__ float  g_T  [NBATCH * NSEQ * DVTOT];

// ---------------------------------------------------------------------------
// helpers
// ---------------------------------------------------------------------------
__device__ __forceinline__ unsigned tf32b(float x) {
    unsigned r;
    asm("cvt.rna.tf32.f32 %0, %1;" : "=r"(r) : "f"(x));
    return r;
}
__device__ __forceinline__ float tf32f(float x) { return __uint_as_float(tf32b(x)); }

__device__ __forceinline__ void mma8(float* c, const unsigned* a, const unsigned* b) {
    asm volatile(
        "mma.sync.aligned.m16n8k8.row.col.f32.tf32.tf32.f32 "
        "{%0,%1,%2,%3},{%4,%5,%6,%7},{%8,%9},{%0,%1,%2,%3};\n"
        : "+f"(c[0]), "+f"(c[1]), "+f"(c[2]), "+f"(c[3])
        : "r"(a[0]), "r"(a[1]), "r"(a[2]), "r"(a[3]), "r"(b[0]), "r"(b[1]));
}
__device__ __forceinline__ void mma16h(float* c, const unsigned* a, const unsigned* b) {
    asm volatile(
        "mma.sync.aligned.m16n8k16.row.col.f32.f16.f16.f32 "
        "{%0,%1,%2,%3},{%4,%5,%6,%7},{%8,%9},{%0,%1,%2,%3};\n"
        : "+f"(c[0]), "+f"(c[1]), "+f"(c[2]), "+f"(c[3])
        : "r"(a[0]), "r"(a[1]), "r"(a[2]), "r"(a[3]), "r"(b[0]), "r"(b[1]));
}
__device__ __forceinline__ unsigned smaddr(const void* p) {
    return (unsigned)__cvta_generic_to_shared(p);
}
__device__ __forceinline__ void ldm_x4(unsigned* r, unsigned a) {
    asm volatile("ldmatrix.sync.aligned.m8n8.x4.shared.b16 {%0,%1,%2,%3},[%4];"
                 : "=r"(r[0]), "=r"(r[1]), "=r"(r[2]), "=r"(r[3]) : "r"(a));
}
__device__ __forceinline__ void ldm_x2(unsigned* r, unsigned a) {
    asm volatile("ldmatrix.sync.aligned.m8n8.x2.shared.b16 {%0,%1},[%2];"
                 : "=r"(r[0]), "=r"(r[1]) : "r"(a));
}
__device__ __forceinline__ void ldm_x2t(unsigned* r, unsigned a) {
    asm volatile("ldmatrix.sync.aligned.m8n8.x2.trans.shared.b16 {%0,%1},[%2];"
                 : "=r"(r[0]), "=r"(r[1]) : "r"(a));
}

// ---------------------------------------------------------------------------
// GEMM: C[8192,512] = A[8192,512] * W[512,512]^T (+bias, epilogues), tf32
// MODE 0: A = Q input; scatter head-major into g_Qh (fp32) + g_Qh16 (fp16)
// MODE 1: A = g_X;  g_T = g_X + relu(C + bias)
// ---------------------------------------------------------------------------
template <int MODE>
__global__ void __launch_bounds__(256) gemm512_kernel(const float* __restrict__ Ain,
                                                      const float* __restrict__ W,
                                                      const float* __restrict__ bias) {
    __shared__ float As[128 * 20];
    __shared__ float Bs[128 * 20];
    const float* A = (MODE == 0) ? Ain : (const float*)g_X;

    const int m0 = blockIdx.y * 128, n0 = blockIdx.x * 128;
    const int tid = threadIdx.x, lane = tid & 31, w = tid >> 5;
    const int wm = (w & 3) * 32, wn = (w >> 2) * 64;

    float acc[2][8][4];
#pragma unroll
    for (int a = 0; a < 2; a++)
#pragma unroll
        for (int b = 0; b < 8; b++)
#pragma unroll
            for (int c = 0; c < 4; c++) acc[a][b][c] = 0.f;

    for (int k0 = 0; k0 < 512; k0 += 16) {
        __syncthreads();
#pragma unroll
        for (int r = 0; r < 2; r++) {
            int idx = tid * 2 + r;
            int row = idx >> 2, kq = (idx & 3) * 4;
            float4 va = *(const float4*)(A + (size_t)(m0 + row) * 512 + k0 + kq);
            As[row * 20 + kq + 0] = tf32f(va.x);
            As[row * 20 + kq + 1] = tf32f(va.y);
            As[row * 20 + kq + 2] = tf32f(va.z);
            As[row * 20 + kq + 3] = tf32f(va.w);
            float4 vb = *(const float4*)(W + (size_t)(n0 + row) * 512 + k0 + kq);
            Bs[row * 20 + kq + 0] = tf32f(vb.x);
            Bs[row * 20 + kq + 1] = tf32f(vb.y);
            Bs[row * 20 + kq + 2] = tf32f(vb.z);
            Bs[row * 20 + kq + 3] = tf32f(vb.w);
        }
        __syncthreads();
#pragma unroll
        for (int kk = 0; kk < 2; kk++) {
            int kc = kk * 8 + (lane & 3);
            unsigned af[2][4];
#pragma unroll
            for (int mt = 0; mt < 2; mt++) {
                int r = wm + mt * 16 + (lane >> 2);
                af[mt][0] = __float_as_uint(As[r * 20 + kc]);
                af[mt][1] = __float_as_uint(As[(r + 8) * 20 + kc]);
                af[mt][2] = __float_as_uint(As[r * 20 + kc + 4]);
                af[mt][3] = __float_as_uint(As[(r + 8) * 20 + kc + 4]);
            }
#pragma unroll
            for (int nt = 0; nt < 8; nt++) {
                int c = wn + nt * 8 + (lane >> 2);
                unsigned bf[2];
                bf[0] = __float_as_uint(Bs[c * 20 + kc]);
                bf[1] = __float_as_uint(Bs[c * 20 + kc + 4]);
#pragma unroll
                for (int mt = 0; mt < 2; mt++) mma8(acc[mt][nt], af[mt], bf);
            }
        }
    }

#pragma unroll
    for (int mt = 0; mt < 2; mt++)
#pragma unroll
        for (int nt = 0; nt < 8; nt++)
#pragma unroll
            for (int rg = 0; rg < 4; rg++) {
                int row = m0 + wm + mt * 16 + (lane >> 2) + ((rg & 2) ? 8 : 0);
                int col = n0 + wn + nt * 8 + 2 * (lane & 3) + (rg & 1);
                float v = acc[mt][nt][rg] + bias[col];
                if (MODE == 0) {
                    int b = row >> 10, i = row & 1023;
                    int h = col >> 6, dc = col & 63;
                    size_t idx = ((size_t)((h << 3) + b) * NSEQ + i) * DHEAD + dc;
                    g_Qh[idx] = v;
                    g_Qh16[idx] = __float2half_rn(v);
                } else {
                    v = fmaxf(v, 0.f) + A[(size_t)row * 512 + col];
                    g_T[(size_t)row * 512 + col] = v;
                }
            }
}

// ---------------------------------------------------------------------------
// Sinkhorn LSE passes, fp16 mma m16n8k16, ldmatrix operand fetch.
// ADDU=false: u_i = log_mu - log(sum_j exp(S_ij))
// ADDU=true : v_j = log_mu - log(sum_i exp(S_ij + u_i))  (S symmetric)
// grid (8, 64), 256 threads, warps 4(m) x 2(j), warp tile 32x64
// ---------------------------------------------------------------------------
template <bool ADDU>
__global__ void __launch_bounds__(256, 2) sink_lse_kernel() {
    __shared__ __align__(16) __half Qi[128 * 72];
    __shared__ __align__(16) __half Qj[128 * 72];
    __shared__ float ub[128];
    __shared__ float ps[256];

    const int bh = blockIdx.y;
    const int i0 = blockIdx.x * 128;
    const int tid = threadIdx.x, lane = tid & 31, w = tid >> 5;
    const int wm = (w & 3) * 32, wn = (w >> 2) * 64;
    const __half* Qbase = g_Qh16 + (size_t)bh * (NSEQ * DHEAD);

    // fill Qi: 128 rows x 64 halves; 8-half chunks
#pragma unroll
    for (int r = 0; r < 4; r++) {
        int idx = tid + r * 256;
        int row = idx >> 3, q = (idx & 7) * 8;
        float4 v = *(const float4*)(Qbase + (i0 + row) * DHEAD + q);
        *(float4*)(Qi + row * 72 + q) = v;
    }
    __syncthreads();

    // hoist A fragments (loop-invariant across j-tiles)
    unsigned af[2][4][4];
#pragma unroll
    for (int mt = 0; mt < 2; mt++)
#pragma unroll
        for (int kk = 0; kk < 4; kk++) {
            int row = wm + mt * 16 + (lane & 15);
            int col = kk * 16 + (lane >> 4) * 8;
            ldm_x4(af[mt][kk], smaddr(Qi + row * 72 + col));
        }

    float ls[2][2] = {{0.f, 0.f}, {0.f, 0.f}};

    for (int jt = 0; jt < 8; jt++) {
        int j0 = jt * 128;
        __syncthreads();
#pragma unroll
        for (int r = 0; r < 4; r++) {
            int idx = tid + r * 256;
            int row = idx >> 3, q = (idx & 7) * 8;
            float4 v = *(const float4*)(Qbase + (j0 + row) * DHEAD + q);
            *(float4*)(Qj + row * 72 + q) = v;
        }
        if (ADDU && tid < 128) ub[tid] = g_u[bh * NSEQ + j0 + tid];
        __syncthreads();

        float sa[2][8][4];
#pragma unroll
        for (int a = 0; a < 2; a++)
#pragma unroll
            for (int b = 0; b < 8; b++)
#pragma unroll
                for (int c = 0; c < 4; c++) sa[a][b][c] = 0.f;

#pragma unroll
        for (int kk = 0; kk < 4; kk++) {
#pragma unroll
            for (int nt = 0; nt < 8; nt++) {
                unsigned bf[2];
                int row = wn + nt * 8 + (lane & 7);
                int col = kk * 16 + ((lane >> 3) & 1) * 8;
                ldm_x2(bf, smaddr(Qj + row * 72 + col));
                mma16h(sa[0][nt], af[0][kk], bf);
                mma16h(sa[1][nt], af[1][kk], bf);
            }
        }
        // accumulate exp sums (no running max: |arg| small)
#pragma unroll
        for (int mt = 0; mt < 2; mt++)
#pragma unroll
            for (int nt = 0; nt < 8; nt++)
#pragma unroll
                for (int rg = 0; rg < 4; rg++) {
                    float v = sa[mt][nt][rg] * SSCALE;
                    if (ADDU) v += ub[wn + nt * 8 + 2 * (lane & 3) + (rg & 1)];
                    ls[mt][rg >> 1] += __expf(v);
                }
    }

#pragma unroll
    for (int mt = 0; mt < 2; mt++)
#pragma unroll
        for (int h = 0; h < 2; h++) {
            float v = ls[mt][h];
            v += __shfl_xor_sync(0xffffffffu, v, 1);
            v += __shfl_xor_sync(0xffffffffu, v, 2);
            if ((lane & 3) == 0)
                ps[(w >> 2) * 128 + wm + mt * 16 + (lane >> 2) + h * 8] = v;
        }
    __syncthreads();
    if (tid < 128) {
        float s = ps[tid] + ps[128 + tid];
        float r = LOGMU - __logf(s);
        if (ADDU) g_v[bh * NSEQ + i0 + tid] = r;
        else      g_u[bh * NSEQ + i0 + tid] = r;
    }
}

// ---------------------------------------------------------------------------
// Pass C: O_ = Q_ + (1024 * exp(S + u_i + v_j)) @ Q_, fp16 mma + ldmatrix
// Phase 1 per j-tile: S via mma (warps 4m x 2j), exp -> Ap (fp16 smem)
// Phase 2: O += Ap @ Qj via mma (warps 4m x 2d)
// ---------------------------------------------------------------------------
__global__ void __launch_bounds__(256, 2) sink_av_kernel() {
    extern __shared__ __align__(16) char smraw[];
    __half* Qi = (__half*)smraw;          // 128*72
    __half* Qj = Qi + 9216;               // 128*72
    __half* Ap = Qj + 9216;               // 128*136
    float* ur = (float*)(Ap + 17408);     // 128
    float* vb = ur + 128;                 // 128

    const int bh = blockIdx.y;
    const int i0 = blockIdx.x * 128;
    const int tid = threadIdx.x, lane = tid & 31, w = tid >> 5;
    const int wm = (w & 3) * 32;
    const int wn = (w >> 2) * 64;    // phase 1 (j cols)
    const int wn2 = (w >> 2) * 32;   // phase 2 (d cols)
    const __half* Qbase = g_Qh16 + (size_t)bh * (NSEQ * DHEAD);
    const float* Qf32 = g_Qh + (size_t)bh * (NSEQ * DHEAD);
    float* Obase = g_Oh + (size_t)bh * (NSEQ * DHEAD);

#pragma unroll
    for (int r = 0; r < 4; r++) {
        int idx = tid + r * 256;
        int row = idx >> 3, q = (idx & 7) * 8;
        float4 v = *(const float4*)(Qbase + (i0 + row) * DHEAD + q);
        *(float4*)(Qi + row * 72 + q) = v;
    }
    if (tid < 128) ur[tid] = g_u[bh * NSEQ + i0 + tid];

    float oa[2][4][4];
#pragma unroll
    for (int a = 0; a < 2; a++)
#pragma unroll
        for (int b = 0; b < 4; b++)
#pragma unroll
            for (int c = 0; c < 4; c++) oa[a][b][c] = 0.f;

    for (int jt = 0; jt < 8; jt++) {
        int j0 = jt * 128;
        __syncthreads();
#pragma unroll
        for (int r = 0; r < 4; r++) {
            int idx = tid + r * 256;
            int row = idx >> 3, q = (idx & 7) * 8;
            float4 v = *(const float4*)(Qbase + (j0 + row) * DHEAD + q);
            *(float4*)(Qj + row * 72 + q) = v;
        }
        if (tid < 128) vb[tid] = g_v[bh * NSEQ + j0 + tid];
        __syncthreads();

        // ---- phase 1: S tile ----
        float sa[2][8][4];
#pragma unroll
        for (int a = 0; a < 2; a++)
#pragma unroll
            for (int b = 0; b < 8; b++)
#pragma unroll
                for (int c = 0; c < 4; c++) sa[a][b][c] = 0.f;

#pragma unroll
        for (int kk = 0; kk < 4; kk++) {
            unsigned a0[4], a1[4];
            {
                int col = kk * 16 + (lane >> 4) * 8;
                ldm_x4(a0, smaddr(Qi + (wm + (lane & 15)) * 72 + col));
                ldm_x4(a1, smaddr(Qi + (wm + 16 + (lane & 15)) * 72 + col));
            }
#pragma unroll
            for (int nt = 0; nt < 8; nt++) {
                unsigned bf[2];
                int row = wn + nt * 8 + (lane & 7);
                int col = kk * 16 + ((lane >> 3) & 1) * 8;
                ldm_x2(bf, smaddr(Qj + row * 72 + col));
                mma16h(sa[0][nt], a0, bf);
                mma16h(sa[1][nt], a1, bf);
            }
        }
        // A = 1024 * exp(S*scale + u_i + v_j) -> fp16 tile Ap
#pragma unroll
        for (int mt = 0; mt < 2; mt++)
#pragma unroll
            for (int nt = 0; nt < 8; nt++) {
                int row0 = wm + mt * 16 + (lane >> 2);
                int col = wn + nt * 8 + 2 * (lane & 3);
                float e0 = 1024.f * __expf(sa[mt][nt][0] * SSCALE + ur[row0] + vb[col]);
                float e1 = 1024.f * __expf(sa[mt][nt][1] * SSCALE + ur[row0] + vb[col + 1]);
                *(__half2*)(Ap + row0 * 136 + col) = __floats2half2_rn(e0, e1);
                int row8 = row0 + 8;
                float e2 = 1024.f * __expf(sa[mt][nt][2] * SSCALE + ur[row8] + vb[col]);
                float e3 = 1024.f * __expf(sa[mt][nt][3] * SSCALE + ur[row8] + vb[col + 1]);
                *(__half2*)(Ap + row8 * 136 + col) = __floats2half2_rn(e2, e3);
            }
        __syncthreads();

        // ---- phase 2: O += Ap @ Qj ----
#pragma unroll
        for (int kk = 0; kk < 8; kk++) {
            unsigned a0[4], a1[4];
            {
                int col = kk * 16 + (lane >> 4) * 8;
                ldm_x4(a0, smaddr(Ap + (wm + (lane & 15)) * 136 + col));
                ldm_x4(a1, smaddr(Ap + (wm + 16 + (lane & 15)) * 136 + col));
            }
#pragma unroll
            for (int nt = 0; nt < 4; nt++) {
                unsigned bf[2];
                int krow = kk * 16 + (lane & 15);
                ldm_x2t(bf, smaddr(Qj + krow * 72 + wn2 + nt * 8));
                mma16h(oa[0][nt], a0, bf);
                mma16h(oa[1][nt], a1, bf);
            }
        }
    }

    // epilogue: O_ = Q_ + accum (residual in fp32)
#pragma unroll
    for (int mt = 0; mt < 2; mt++)
#pragma unroll
        for (int nt = 0; nt < 4; nt++)
#pragma unroll
            for (int rg = 0; rg < 4; rg++) {
                int row = i0 + wm + mt * 16 + (lane >> 2) + ((rg & 2) ? 8 : 0);
                int col = wn2 + nt * 8 + 2 * (lane & 3) + (rg & 1);
                Obase[row * DHEAD + col] = oa[mt][nt][rg] + Qf32[row * DHEAD + col];
            }
}

// ---------------------------------------------------------------------------
// LayerNorm. mode 0: merge heads g_Oh -> LN -> g_X ; mode 1: g_T -> LN -> out
// ---------------------------------------------------------------------------
__global__ void __launch_bounds__(512) ln_kernel(const float* __restrict__ gg,
                                                 const float* __restrict__ bb,
                                                 float* __restrict__ out, int mode) {
    int m = blockIdx.x;
    int t = threadIdx.x;
    float val;
    if (mode == 0) {
        int b = m >> 10, i = m & 1023, h = t >> 6, dc = t & 63;
        val = g_Oh[(((h << 3) + b) * NSEQ + i) * DHEAD + dc];
    } else {
        val = g_T[(size_t)m * 512 + t];
    }
    float s = val, q = val * val;
#pragma unroll
    for (int off = 16; off; off >>= 1) {
        s += __shfl_xor_sync(0xffffffffu, s, off);
        q += __shfl_xor_sync(0xffffffffu, q, off);
    }
    __shared__ float ss[16], sq[16];
    int w = t >> 5, lane = t & 31;
    if (!lane) { ss[w] = s; sq[w] = q; }
    __syncthreads();
    float S = 0.f, Q2 = 0.f;
#pragma unroll
    for (int k = 0; k < 16; k++) { S += ss[k]; Q2 += sq[k]; }
    float mean = S * (1.f / 512.f);
    float var = Q2 * (1.f / 512.f) - mean * mean;
    float y = (val - mean) * rsqrtf(var + 1e-5f) * gg[t] + bb[t];
    if (mode == 0) g_X[(size_t)m * 512 + t] = y;
    else           out[(size_t)m * 512 + t] = y;
}

// ---------------------------------------------------------------------------
extern "C" void kernel_launch(void* const* d_in, const int* in_sizes, int n_in,
                              void* d_out, int out_size) {
    (void)in_sizes; (void)n_in; (void)out_size;
    const float* Q  = (const float*)d_in[0];
    // d_in[1] = K, unused by the reference forward
    const float* Wq = (const float*)d_in[2];
    const float* bq = (const float*)d_in[3];
    const float* Wo = (const float*)d_in[4];
    const float* bo = (const float*)d_in[5];
    const float* g0 = (const float*)d_in[6];
    const float* b0 = (const float*)d_in[7];
    const float* g1 = (const float*)d_in[8];
    const float* b1 = (const float*)d_in[9];
    float* out = (float*)d_out;

    const int SMEM_AV = (9216 + 9216 + 17408) * 2 + 256 * 4;  // 72704 B
    cudaFuncSetAttribute(sink_av_kernel,
                         cudaFuncAttributeMaxDynamicSharedMemorySize, SMEM_AV);

    dim3 ggrid(4, 64);   // N/128, M/128
    dim3 agrid(8, 64);   // row-blocks, bh

    gemm512_kernel<0><<<ggrid, 256>>>(Q, Wq, bq);
    sink_lse_kernel<false><<<agrid, 256>>>();
    sink_lse_kernel<true><<<agrid, 256>>>();
    sink_av_kernel<<<agrid, 256, SMEM_AV>>>();
    ln_kernel<<<8192, 512>>>(g0, b0, nullptr, 0);
    gemm512_kernel<1><<<ggrid, 256>>>(nullptr, Wo, bo);
    ln_kernel<<<8192, 512>>>(g1, b1, out, 1);
}